// round 9
// baseline (speedup 1.0000x reference)
#include <cuda_runtime.h>
#include <cuda_bf16.h>
#include <math.h>
#include <stdint.h>

#define B    8
#define NTOK 2048
#define FIN  256
#define D    128
#define ALPHA 0.2f
#define CHUNK  16
#define NCHUNK (NTOK/CHUNK)   // 128

// ---------------- scratch (__device__ globals) --------------------------------
__device__ float d_Wh[B*NTOK*D];
__device__ float d_s1[B*NTOK];
__device__ float d_s2[B*NTOK];
__device__ float d_ss1[B*NTOK];
__device__ float d_pe[B*NTOK];
__device__ float d_pa[B*NTOK];
__device__ float d_s2s[B*NTOK];
__device__ int   d_perm[B*NTOK];
__device__ float d_g1[B*NTOK];
__device__ float d_g2[B*NTOK];
__device__ int   d_tq[B*NTOK];
__device__ float d_e1[B*NTOK];
__device__ float d_e2[B*NTOK];
__device__ float d_loc12[B*NTOK*D*2];      // interleaved (v1,v2) prefix pairs
__device__ float d_ct1[B*NCHUNK*D];
__device__ float d_ct2[B*NCHUNK*D];
__device__ float d_cp12[B*NCHUNK*D*2];     // interleaved chunk offsets
__device__ float d_tot1[B*D];
__device__ __nv_bfloat16 d_Wt_hi[D*FIN];
__device__ __nv_bfloat16 d_Wt_lo[D*FIN];

// ================= mma.sync helpers ============================================
__device__ __forceinline__ uint32_t smem_u32(const void* p) {
    uint32_t a;
    asm("{ .reg .u64 t; cvta.to.shared.u64 t, %1; cvt.u32.u64 %0, t; }" : "=r"(a) : "l"(p));
    return a;
}
__device__ __forceinline__ void ldm_x4(uint32_t& r0, uint32_t& r1, uint32_t& r2, uint32_t& r3, uint32_t addr) {
    asm volatile("ldmatrix.sync.aligned.m8n8.x4.shared.b16 {%0,%1,%2,%3}, [%4];"
        : "=r"(r0), "=r"(r1), "=r"(r2), "=r"(r3) : "r"(addr));
}
__device__ __forceinline__ void mma_bf16(float* c, const uint32_t* a, uint32_t b0, uint32_t b1) {
    asm volatile("mma.sync.aligned.m16n8k16.row.col.f32.bf16.bf16.f32 "
        "{%0,%1,%2,%3},{%4,%5,%6,%7},{%8,%9},{%0,%1,%2,%3};"
        : "+f"(c[0]), "+f"(c[1]), "+f"(c[2]), "+f"(c[3])
        : "r"(a[0]), "r"(a[1]), "r"(a[2]), "r"(a[3]), "r"(b0), "r"(b1));
}

// smem layout (bytes). Rows padded to 72 bf16 (144 B).
#define KT      64
#define ROWB    144
#define AH_OFF  0
#define AL_OFF  9216
#define BH_OFF  18432
#define BL_OFF  36864
#define A1_OFF  55296
#define A2_OFF  55808
#define PS1_OFF 56320
#define PS2_OFF 56832
#define SM_TOT  57344

// ---------------- K0: W -> bf16 hi/lo, transposed [n][k] ----------------------
__global__ void __launch_bounds__(256) k_wconv(const float* __restrict__ W)
{
    int idx = blockIdx.x * 256 + threadIdx.x;
    int k = idx & 255;
    int n = idx >> 8;
    float x = W[(size_t)k * D + n];
    __nv_bfloat16 hi = __float2bfloat16_rn(x);
    __nv_bfloat16 lo = __float2bfloat16_rn(x - __bfloat162float(hi));
    d_Wt_hi[n * FIN + k] = hi;
    d_Wt_lo[n * FIN + k] = lo;
}

// ---------------- K1: Wh = h@W via mma.sync bf16x3 (64x128 tile) --------------
__global__ void __launch_bounds__(256, 2)
k_gemm_mma(const float* __restrict__ h, const float* __restrict__ a)
{
    extern __shared__ char smem[];
    const uint32_t sb = smem_u32(smem);
    const int tid  = threadIdx.x;
    const int wid  = tid >> 5;
    const int lane = tid & 31;
    const int rowBase = blockIdx.x * 64;

    float* a1s = (float*)(smem + A1_OFF);
    float* a2s = (float*)(smem + A2_OFF);
    float* ps1 = (float*)(smem + PS1_OFF);
    float* ps2 = (float*)(smem + PS2_OFF);

    if (tid < 128) {
        a1s[tid] = a[tid];
        a2s[tid] = a[128 + tid];
    }

    const int mb0 = (wid & 3) * 16;
    const int nbh = wid >> 2;
    const int nb  = nbh * 64;

    float acc[8][4] = {};

    for (int t = 0; t < 4; t++) {
        const int kt = t * KT;
        __syncthreads();

        #pragma unroll
        for (int l = 0; l < 4; l++) {
            int f4 = tid + l * 256;
            int r  = f4 >> 4;
            int c  = (f4 & 15) * 4;
            float4 v = *(const float4*)&h[(size_t)(rowBase + r) * FIN + kt + c];
            __nv_bfloat162 h0 = __floats2bfloat162_rn(v.x, v.y);
            __nv_bfloat162 h1 = __floats2bfloat162_rn(v.z, v.w);
            __nv_bfloat162 l0 = __floats2bfloat162_rn(v.x - __bfloat162float(h0.x),
                                                      v.y - __bfloat162float(h0.y));
            __nv_bfloat162 l1 = __floats2bfloat162_rn(v.z - __bfloat162float(h1.x),
                                                      v.w - __bfloat162float(h1.y));
            uint32_t off = (uint32_t)r * ROWB + (uint32_t)c * 2;
            *(uint2*)(smem + AH_OFF + off) = make_uint2(*(uint32_t*)&h0, *(uint32_t*)&h1);
            *(uint2*)(smem + AL_OFF + off) = make_uint2(*(uint32_t*)&l0, *(uint32_t*)&l1);
        }
        #pragma unroll
        for (int l = 0; l < 4; l++) {
            int u  = tid + l * 256;
            int n  = u >> 3;
            int ch = (u & 7) * 16;
            uint32_t dst = (uint32_t)n * ROWB + (uint32_t)ch;
            const char* srch = (const char*)&d_Wt_hi[n * FIN + kt] + ch;
            const char* srcl = (const char*)&d_Wt_lo[n * FIN + kt] + ch;
            *(uint4*)(smem + BH_OFF + dst) = *(const uint4*)srch;
            *(uint4*)(smem + BL_OFF + dst) = *(const uint4*)srcl;
        }
        __syncthreads();

        #pragma unroll
        for (int ks = 0; ks < 4; ks++) {
            const uint32_t colB = (uint32_t)ks * 32 + (uint32_t)(lane >> 4) * 16;
            uint32_t a_hi[4], a_lo[4];
            {
                uint32_t roff = (uint32_t)(mb0 + (lane & 15)) * ROWB + colB;
                ldm_x4(a_hi[0], a_hi[1], a_hi[2], a_hi[3], sb + AH_OFF + roff);
                ldm_x4(a_lo[0], a_lo[1], a_lo[2], a_lo[3], sb + AL_OFF + roff);
            }
            #pragma unroll
            for (int g = 0; g < 4; g++) {
                uint32_t roff = (uint32_t)(nb + g * 16 + (lane & 15)) * ROWB + colB;
                uint32_t b0, b1, b2, b3;
                ldm_x4(b0, b1, b2, b3, sb + BH_OFF + roff);
                mma_bf16(acc[g * 2],     a_hi, b0, b2);
                mma_bf16(acc[g * 2 + 1], a_hi, b1, b3);
                mma_bf16(acc[g * 2],     a_lo, b0, b2);
                mma_bf16(acc[g * 2 + 1], a_lo, b1, b3);
                ldm_x4(b0, b1, b2, b3, sb + BL_OFF + roff);
                mma_bf16(acc[g * 2],     a_hi, b0, b2);
                mma_bf16(acc[g * 2 + 1], a_hi, b1, b3);
            }
        }
    }
    __syncthreads();

    {
        const int r0 = mb0 + (lane >> 2);
        const int r1 = r0 + 8;
        float p1a = 0.f, p2a = 0.f, p1b = 0.f, p2b = 0.f;
        #pragma unroll
        for (int nt = 0; nt < 8; nt++) {
            const int col = nb + nt * 8 + (lane & 3) * 2;
            float c0 = acc[nt][0], c1 = acc[nt][1];
            float c2 = acc[nt][2], c3 = acc[nt][3];
            *(float2*)&d_Wh[(size_t)(rowBase + r0) * D + col] = make_float2(c0, c1);
            *(float2*)&d_Wh[(size_t)(rowBase + r1) * D + col] = make_float2(c2, c3);
            p1a += c0 * a1s[col] + c1 * a1s[col + 1];
            p2a += c0 * a2s[col] + c1 * a2s[col + 1];
            p1b += c2 * a1s[col] + c3 * a1s[col + 1];
            p2b += c2 * a2s[col] + c3 * a2s[col + 1];
        }
        #pragma unroll
        for (int o = 1; o <= 2; o <<= 1) {
            p1a += __shfl_xor_sync(0xffffffffu, p1a, o);
            p2a += __shfl_xor_sync(0xffffffffu, p2a, o);
            p1b += __shfl_xor_sync(0xffffffffu, p1b, o);
            p2b += __shfl_xor_sync(0xffffffffu, p2b, o);
        }
        if ((lane & 3) == 0) {
            ps1[nbh * 64 + r0] = p1a;  ps2[nbh * 64 + r0] = p2a;
            ps1[nbh * 64 + r1] = p1b;  ps2[nbh * 64 + r1] = p2b;
        }
    }
    __syncthreads();
    if (tid < 64) {
        d_s1[rowBase + tid] = ps1[tid] + ps1[64 + tid];
        d_s2[rowBase + tid] = ps2[tid] + ps2[64 + tid];
    }
}

// ------- K2a: hybrid register/shuffle bitonic sort + fused i-side searches -----
__global__ void __launch_bounds__(1024) k_sort()
{
    __shared__ float sk[NTOK];
    __shared__ int   sx[NTOK];
    __shared__ float wsum[64];

    const int role = blockIdx.x, b = blockIdx.y, tid = threadIdx.x;
    const int lane = tid & 31, wid = tid >> 5;
    const float* src = (role == 0 ? d_s1 : d_s2) + b * NTOK;

    float2 v0 = *(const float2*)&src[2 * tid];
    float k0 = v0.x, k1 = v0.y;
    int   x0 = 2 * tid, x1 = 2 * tid + 1;

    #pragma unroll
    for (int k = 2; k <= 64; k <<= 1) {
        const bool up = (((tid << 1) & k) == 0);
        #pragma unroll
        for (int j = k >> 1; j >= 2; j >>= 1) {
            const int m = j >> 1;
            float pk0 = __shfl_xor_sync(~0u, k0, m);
            float pk1 = __shfl_xor_sync(~0u, k1, m);
            int   px0 = __shfl_xor_sync(~0u, x0, m);
            int   px1 = __shfl_xor_sync(~0u, x1, m);
            const bool lo = ((tid & m) == 0);
            float lk = lo ? k0 : pk0, hk = lo ? pk0 : k0;
            if ((lk > hk) == up) { k0 = pk0; x0 = px0; }
            lk = lo ? k1 : pk1; hk = lo ? pk1 : k1;
            if ((lk > hk) == up) { k1 = pk1; x1 = px1; }
        }
        if ((k0 > k1) == up) {
            float tk = k0; k0 = k1; k1 = tk;
            int   tx = x0; x0 = x1; x1 = tx;
        }
    }

    #pragma unroll 1
    for (int k = 128; k <= 2048; k <<= 1) {
        sk[2 * tid] = k0; sk[2 * tid + 1] = k1;
        sx[2 * tid] = x0; sx[2 * tid + 1] = x1;
        __syncthreads();
        #pragma unroll 1
        for (int j = k >> 1; j >= 64; j >>= 1) {
            if ((tid & (j >> 1)) == 0) {
                const bool up = (((tid << 1) & k) == 0);
                #pragma unroll
                for (int bb = 0; bb < 2; bb++) {
                    int i = 2 * tid + bb, p = i ^ j;
                    float A = sk[i], Bv = sk[p];
                    if ((A > Bv) == up) {
                        sk[i] = Bv; sk[p] = A;
                        int tI = sx[i]; sx[i] = sx[p]; sx[p] = tI;
                    }
                }
            }
            __syncthreads();
        }
        k0 = sk[2 * tid]; k1 = sk[2 * tid + 1];
        x0 = sx[2 * tid]; x1 = sx[2 * tid + 1];
        const bool up = (((tid << 1) & k) == 0);
        #pragma unroll
        for (int j = 32; j >= 2; j >>= 1) {
            const int m = j >> 1;
            float pk0 = __shfl_xor_sync(~0u, k0, m);
            float pk1 = __shfl_xor_sync(~0u, k1, m);
            int   px0 = __shfl_xor_sync(~0u, x0, m);
            int   px1 = __shfl_xor_sync(~0u, x1, m);
            const bool lo = ((tid & m) == 0);
            float lk = lo ? k0 : pk0, hk = lo ? pk0 : k0;
            if ((lk > hk) == up) { k0 = pk0; x0 = px0; }
            lk = lo ? k1 : pk1; hk = lo ? pk1 : k1;
            if ((lk > hk) == up) { k1 = pk1; x1 = px1; }
        }
        if ((k0 > k1) == up) {
            float tk = k0; k0 = k1; k1 = tk;
            int   tx = x0; x0 = x1; x1 = tx;
        }
    }

    if (role == 1) {
        *(float2*)&d_s2s[b * NTOK + 2 * tid]  = make_float2(k0, k1);
        *(int2*)  &d_perm[b * NTOK + 2 * tid] = make_int2(x0, x1);

        // fused i-side: sorted s2 -> smem, per-query threshold + exps
        sk[2 * tid] = k0; sk[2 * tid + 1] = k1;
        __syncthreads();
        #pragma unroll
        for (int q = 0; q < 2; q++) {
            int i = tid + q * 1024;
            float s1v = d_s1[b * NTOK + i];
            float keyv = -s1v;
            int lo = 0;
            #pragma unroll
            for (int step = 1024; step >= 1; step >>= 1) {
                int probe = lo + step - 1;
                if (probe < NTOK && sk[probe] < keyv) lo += step;
            }
            d_tq[b * NTOK + i] = lo;
            d_e1[b * NTOK + i] = expf(s1v);
            d_e2[b * NTOK + i] = expf(ALPHA * s1v);
        }
        return;
    }

    const float e0 = expf(k0), e1 = expf(k1);
    const float a0 = expf(ALPHA * k0), a1 = expf(ALPHA * k1);
    float ie = e0 + e1, ia = a0 + a1;
    #pragma unroll
    for (int o = 1; o < 32; o <<= 1) {
        float te = __shfl_up_sync(~0u, ie, o);
        float ta = __shfl_up_sync(~0u, ia, o);
        if (lane >= o) { ie += te; ia += ta; }
    }
    if (lane == 31) { wsum[wid] = ie; wsum[32 + wid] = ia; }
    __syncthreads();
    if (wid == 0) {
        float we = wsum[lane], wa = wsum[32 + lane];
        #pragma unroll
        for (int o = 1; o < 32; o <<= 1) {
            float te = __shfl_up_sync(~0u, we, o);
            float ta = __shfl_up_sync(~0u, wa, o);
            if (lane >= o) { we += te; wa += ta; }
        }
        wsum[lane] = we; wsum[32 + lane] = wa;
    }
    __syncthreads();
    const float offE = (wid > 0 ? wsum[wid - 1] : 0.f);
    const float offA = (wid > 0 ? wsum[32 + wid - 1] : 0.f);
    const float peI = offE + ie;
    const float paI = offA + ia;

    *(float2*)&d_ss1[b * NTOK + 2 * tid] = make_float2(k0, k1);
    *(float2*)&d_pe[b * NTOK + 2 * tid]  = make_float2(peI - e1, peI);
    *(float2*)&d_pa[b * NTOK + 2 * tid]  = make_float2(paI - a1, paI);
}

// ------- K2b: j-side g1/g2, smem-staged ss1, 128 blocks ------------------------
__global__ void __launch_bounds__(128) k_gfill()
{
    __shared__ float ss1[NTOK];

    const int b = blockIdx.y, tid = threadIdx.x;
    const int idx = blockIdx.x * 128 + tid;

    #pragma unroll
    for (int l = 0; l < 4; l++) {
        int f4 = tid + l * 128;
        *(float4*)&ss1[f4 * 4] = *(const float4*)&d_ss1[b * NTOK + f4 * 4];
    }
    __syncthreads();

    float s2v = __ldg(&d_s2s[b * NTOK + idx]);
    float keyv = -s2v;
    int lo = 0;
    #pragma unroll
    for (int step = 1024; step >= 1; step >>= 1) {
        int probe = lo + step - 1;
        if (probe < NTOK && ss1[probe] < keyv) lo += step;
    }
    const float totE = __ldg(&d_pe[b * NTOK + NTOK - 1]);
    float preE = lo > 0 ? __ldg(&d_pe[b * NTOK + lo - 1]) : 0.f;
    float preA = lo > 0 ? __ldg(&d_pa[b * NTOK + lo - 1]) : 0.f;
    float e2  = expf(s2v);
    float ea2 = expf(ALPHA * s2v);
    float inv = 1.f / (e2 * (totE - preE) + ea2 * preA);
    d_g1[b * NTOK + idx] = e2  * inv;
    d_g2[b * NTOK + idx] = ea2 * inv;
}

// ------- K3: chunk-local prefix sums, interleaved STG.64 stores ----------------
__global__ void __launch_bounds__(128) k_scan()
{
    __shared__ int   sp[CHUNK];
    __shared__ float sg1[CHUNK], sg2[CHUNK];

    const int b = blockIdx.y, c = blockIdx.x, d = threadIdx.x;
    const int base = b * NTOK + c * CHUNK;

    if (d < CHUNK)           sp [d]             = d_perm[base + d];
    else if (d < 2 * CHUNK)  sg1[d - CHUNK]     = d_g1[base + d - CHUNK];
    else if (d < 3 * CHUNK)  sg2[d - 2 * CHUNK] = d_g2[base + d - 2 * CHUNK];
    __syncthreads();

    float w[CHUNK];
    #pragma unroll
    for (int r = 0; r < CHUNK; r++)
        w[r] = d_Wh[((size_t)b * NTOK + sp[r]) * D + d];

    float s1a = 0.f, s2a = 0.f;
    #pragma unroll
    for (int r = 0; r < CHUNK; r++) {
        s1a += sg1[r] * w[r];
        s2a += sg2[r] * w[r];
        *(float2*)&d_loc12[((size_t)(base + r) * D + d) * 2] = make_float2(s1a, s2a);
    }
    d_ct1[(b * NCHUNK + c) * D + d] = s1a;
    d_ct2[(b * NCHUNK + c) * D + d] = s2a;
}

// ------- K4: two-phase exclusive scan of 128 chunk totals ---------------------
__global__ void __launch_bounds__(1024) k_coff()
{
    __shared__ float part1[8][D];
    __shared__ float part2[8][D];

    const int b = blockIdx.x;
    const int d = threadIdx.x & 127;
    const int g = threadIdx.x >> 7;

    float v1[16], v2[16];
    #pragma unroll
    for (int r = 0; r < 16; r++) {
        int c = g * 16 + r;
        v1[r] = d_ct1[(b * NCHUNK + c) * D + d];
        v2[r] = d_ct2[(b * NCHUNK + c) * D + d];
    }
    float run1 = 0.f, run2 = 0.f;
    #pragma unroll
    for (int r = 0; r < 16; r++) {
        float t1 = v1[r]; v1[r] = run1; run1 += t1;
        float t2 = v2[r]; v2[r] = run2; run2 += t2;
    }
    part1[g][d] = run1;
    part2[g][d] = run2;
    __syncthreads();

    if (g == 0) {
        float r1 = 0.f, r2 = 0.f;
        #pragma unroll
        for (int gg = 0; gg < 8; gg++) {
            float t1 = part1[gg][d]; part1[gg][d] = r1; r1 += t1;
            float t2 = part2[gg][d]; part2[gg][d] = r2; r2 += t2;
        }
        d_tot1[b * D + d] = r1;
    }
    __syncthreads();

    const float o1 = part1[g][d];
    const float o2 = part2[g][d];
    #pragma unroll
    for (int r = 0; r < 16; r++) {
        int c = g * 16 + r;
        *(float2*)&d_cp12[((size_t)(b * NCHUNK + c) * D + d) * 2] = make_float2(o1 + v1[r], o2 + v2[r]);
    }
}

// ------- K5: wide gather + ELU (interleaved loc/cp reads) ----------------------
__global__ void __launch_bounds__(256) k_out(float* __restrict__ out)
{
    const int gq   = blockIdx.x * 8 + (threadIdx.x >> 5);
    const int lane = threadIdx.x & 31;
    const int b    = gq >> 11;
    const int d4   = lane * 4;

    const int   t  = d_tq[gq];
    const float e1 = d_e1[gq];
    const float e2 = d_e2[gq];

    float4 tot = *(const float4*)&d_tot1[b * D + d4];
    float4 P1 = {0.f, 0.f, 0.f, 0.f};
    float4 P2 = {0.f, 0.f, 0.f, 0.f};

    if (t > 0) {
        int k = t - 1;
        int c = k >> 4;
        size_t kb = ((size_t)(b * NTOK + k) * D + d4) * 2;
        size_t cb = ((size_t)(b * NCHUNK + c) * D + d4) * 2;
        float4 u0 = *(const float4*)&d_loc12[kb];
        float4 u1 = *(const float4*)&d_loc12[kb + 4];
        float4 q0 = *(const float4*)&d_cp12[cb];
        float4 q1 = *(const float4*)&d_cp12[cb + 4];
        P1.x = u0.x + q0.x; P2.x = u0.y + q0.y;
        P1.y = u0.z + q0.z; P2.y = u0.w + q0.w;
        P1.z = u1.x + q1.x; P2.z = u1.y + q1.y;
        P1.w = u1.z + q1.z; P2.w = u1.w + q1.w;
    }

    float4 v;
    v.x = e1 * (tot.x - P1.x) + e2 * P2.x;
    v.y = e1 * (tot.y - P1.y) + e2 * P2.y;
    v.z = e1 * (tot.z - P1.z) + e2 * P2.z;
    v.w = e1 * (tot.w - P1.w) + e2 * P2.w;
    v.x = v.x > 0.f ? v.x : expm1f(v.x);
    v.y = v.y > 0.f ? v.y : expm1f(v.y);
    v.z = v.z > 0.f ? v.z : expm1f(v.z);
    v.w = v.w > 0.f ? v.w : expm1f(v.w);

    *(float4*)&out[(size_t)gq * D + d4] = v;
}

// -----------------------------------------------------------------------------
extern "C" void kernel_launch(void* const* d_in, const int* in_sizes, int n_in,
                              void* d_out, int out_size)
{
    const float* h = (const float*)d_in[0];   // [8,2048,256]
    const float* W = (const float*)d_in[1];   // [256,128]
    const float* a = (const float*)d_in[2];   // [256,1]
    float* out = (float*)d_out;               // [8,2048,128]

    cudaFuncSetAttribute(k_gemm_mma, cudaFuncAttributeMaxDynamicSharedMemorySize, SM_TOT);

    k_wconv<<<FIN * D / 256, 256>>>(W);
    k_gemm_mma<<<(B * NTOK) / 64, 256, SM_TOT>>>(h, a);
    k_sort <<<dim3(2, B), 1024>>>();
    k_gfill<<<dim3(NTOK / 128, B), 128>>>();
    k_scan <<<dim3(NCHUNK, B), 128>>>();
    k_coff <<<B, 1024>>>();
    k_out  <<<(B * NTOK) / 8, 256>>>(out);
}

// round 10
// speedup vs baseline: 1.0861x; 1.0861x over previous
#include <cuda_runtime.h>
#include <cuda_bf16.h>
#include <math.h>
#include <stdint.h>

#define B    8
#define NTOK 2048
#define FIN  256
#define D    128
#define ALPHA 0.2f
#define CHUNK  16
#define NCHUNK (NTOK/CHUNK)   // 128

// ---------------- scratch (__device__ globals) --------------------------------
__device__ float d_Wh[B*NTOK*D];
__device__ float d_s1[B*NTOK];
__device__ float d_s2[B*NTOK];
__device__ float d_ss1[B*NTOK];
__device__ float d_pe[B*NTOK];
__device__ float d_pa[B*NTOK];
__device__ float d_s2s[B*NTOK];
__device__ int   d_perm[B*NTOK];
__device__ float d_g1[B*NTOK];
__device__ float d_g2[B*NTOK];
__device__ int   d_tq[B*NTOK];
__device__ float d_e1[B*NTOK];
__device__ float d_e2[B*NTOK];
__device__ float d_loc12[B*NTOK*D*2];      // interleaved (v1,v2) prefix pairs
__device__ float d_ct1[B*NCHUNK*D];
__device__ float d_ct2[B*NCHUNK*D];
__device__ float d_cp12[B*NCHUNK*D*2];     // interleaved chunk offsets
__device__ float d_tot1[B*D];
__device__ __nv_bfloat16 d_Wt_hi[D*FIN];
__device__ __nv_bfloat16 d_Wt_lo[D*FIN];

// ================= mma.sync helpers ============================================
__device__ __forceinline__ uint32_t smem_u32(const void* p) {
    uint32_t a;
    asm("{ .reg .u64 t; cvta.to.shared.u64 t, %1; cvt.u32.u64 %0, t; }" : "=r"(a) : "l"(p));
    return a;
}
__device__ __forceinline__ void ldm_x4(uint32_t& r0, uint32_t& r1, uint32_t& r2, uint32_t& r3, uint32_t addr) {
    asm volatile("ldmatrix.sync.aligned.m8n8.x4.shared.b16 {%0,%1,%2,%3}, [%4];"
        : "=r"(r0), "=r"(r1), "=r"(r2), "=r"(r3) : "r"(addr));
}
__device__ __forceinline__ void mma_bf16(float* c, const uint32_t* a, uint32_t b0, uint32_t b1) {
    asm volatile("mma.sync.aligned.m16n8k16.row.col.f32.bf16.bf16.f32 "
        "{%0,%1,%2,%3},{%4,%5,%6,%7},{%8,%9},{%0,%1,%2,%3};"
        : "+f"(c[0]), "+f"(c[1]), "+f"(c[2]), "+f"(c[3])
        : "r"(a[0]), "r"(a[1]), "r"(a[2]), "r"(a[3]), "r"(b0), "r"(b1));
}

// smem layout (bytes). Rows padded to 72 bf16 (144 B).
#define KT      64
#define ROWB    144
#define AH_OFF  0
#define AL_OFF  9216
#define BH_OFF  18432
#define BL_OFF  36864
#define A1_OFF  55296
#define A2_OFF  55808
#define PS1_OFF 56320
#define PS2_OFF 56832
#define SM_TOT  57344

// ---------------- K0: W -> bf16 hi/lo, transposed [n][k] ----------------------
__global__ void __launch_bounds__(256) k_wconv(const float* __restrict__ W)
{
    int idx = blockIdx.x * 256 + threadIdx.x;
    int k = idx & 255;
    int n = idx >> 8;
    float x = W[(size_t)k * D + n];
    __nv_bfloat16 hi = __float2bfloat16_rn(x);
    __nv_bfloat16 lo = __float2bfloat16_rn(x - __bfloat162float(hi));
    d_Wt_hi[n * FIN + k] = hi;
    d_Wt_lo[n * FIN + k] = lo;
}

// ---------------- K1: Wh = h@W via mma.sync bf16x3 (64x128 tile) --------------
__global__ void __launch_bounds__(256, 2)
k_gemm_mma(const float* __restrict__ h, const float* __restrict__ a)
{
    extern __shared__ char smem[];
    const uint32_t sb = smem_u32(smem);
    const int tid  = threadIdx.x;
    const int wid  = tid >> 5;
    const int lane = tid & 31;
    const int rowBase = blockIdx.x * 64;

    float* a1s = (float*)(smem + A1_OFF);
    float* a2s = (float*)(smem + A2_OFF);
    float* ps1 = (float*)(smem + PS1_OFF);
    float* ps2 = (float*)(smem + PS2_OFF);

    if (tid < 128) {
        a1s[tid] = a[tid];
        a2s[tid] = a[128 + tid];
    }

    const int mb0 = (wid & 3) * 16;
    const int nbh = wid >> 2;
    const int nb  = nbh * 64;

    float acc[8][4] = {};

    for (int t = 0; t < 4; t++) {
        const int kt = t * KT;
        __syncthreads();

        #pragma unroll
        for (int l = 0; l < 4; l++) {
            int f4 = tid + l * 256;
            int r  = f4 >> 4;
            int c  = (f4 & 15) * 4;
            float4 v = *(const float4*)&h[(size_t)(rowBase + r) * FIN + kt + c];
            __nv_bfloat162 h0 = __floats2bfloat162_rn(v.x, v.y);
            __nv_bfloat162 h1 = __floats2bfloat162_rn(v.z, v.w);
            __nv_bfloat162 l0 = __floats2bfloat162_rn(v.x - __bfloat162float(h0.x),
                                                      v.y - __bfloat162float(h0.y));
            __nv_bfloat162 l1 = __floats2bfloat162_rn(v.z - __bfloat162float(h1.x),
                                                      v.w - __bfloat162float(h1.y));
            uint32_t off = (uint32_t)r * ROWB + (uint32_t)c * 2;
            *(uint2*)(smem + AH_OFF + off) = make_uint2(*(uint32_t*)&h0, *(uint32_t*)&h1);
            *(uint2*)(smem + AL_OFF + off) = make_uint2(*(uint32_t*)&l0, *(uint32_t*)&l1);
        }
        #pragma unroll
        for (int l = 0; l < 4; l++) {
            int u  = tid + l * 256;
            int n  = u >> 3;
            int ch = (u & 7) * 16;
            uint32_t dst = (uint32_t)n * ROWB + (uint32_t)ch;
            const char* srch = (const char*)&d_Wt_hi[n * FIN + kt] + ch;
            const char* srcl = (const char*)&d_Wt_lo[n * FIN + kt] + ch;
            *(uint4*)(smem + BH_OFF + dst) = *(const uint4*)srch;
            *(uint4*)(smem + BL_OFF + dst) = *(const uint4*)srcl;
        }
        __syncthreads();

        #pragma unroll
        for (int ks = 0; ks < 4; ks++) {
            const uint32_t colB = (uint32_t)ks * 32 + (uint32_t)(lane >> 4) * 16;
            uint32_t a_hi[4], a_lo[4];
            {
                uint32_t roff = (uint32_t)(mb0 + (lane & 15)) * ROWB + colB;
                ldm_x4(a_hi[0], a_hi[1], a_hi[2], a_hi[3], sb + AH_OFF + roff);
                ldm_x4(a_lo[0], a_lo[1], a_lo[2], a_lo[3], sb + AL_OFF + roff);
            }
            #pragma unroll
            for (int g = 0; g < 4; g++) {
                uint32_t roff = (uint32_t)(nb + g * 16 + (lane & 15)) * ROWB + colB;
                uint32_t b0, b1, b2, b3;
                ldm_x4(b0, b1, b2, b3, sb + BH_OFF + roff);
                mma_bf16(acc[g * 2],     a_hi, b0, b2);
                mma_bf16(acc[g * 2 + 1], a_hi, b1, b3);
                mma_bf16(acc[g * 2],     a_lo, b0, b2);
                mma_bf16(acc[g * 2 + 1], a_lo, b1, b3);
                ldm_x4(b0, b1, b2, b3, sb + BL_OFF + roff);
                mma_bf16(acc[g * 2],     a_hi, b0, b2);
                mma_bf16(acc[g * 2 + 1], a_hi, b1, b3);
            }
        }
    }
    __syncthreads();

    {
        const int r0 = mb0 + (lane >> 2);
        const int r1 = r0 + 8;
        float p1a = 0.f, p2a = 0.f, p1b = 0.f, p2b = 0.f;
        #pragma unroll
        for (int nt = 0; nt < 8; nt++) {
            const int col = nb + nt * 8 + (lane & 3) * 2;
            float c0 = acc[nt][0], c1 = acc[nt][1];
            float c2 = acc[nt][2], c3 = acc[nt][3];
            *(float2*)&d_Wh[(size_t)(rowBase + r0) * D + col] = make_float2(c0, c1);
            *(float2*)&d_Wh[(size_t)(rowBase + r1) * D + col] = make_float2(c2, c3);
            p1a += c0 * a1s[col] + c1 * a1s[col + 1];
            p2a += c0 * a2s[col] + c1 * a2s[col + 1];
            p1b += c2 * a1s[col] + c3 * a1s[col + 1];
            p2b += c2 * a2s[col] + c3 * a2s[col + 1];
        }
        #pragma unroll
        for (int o = 1; o <= 2; o <<= 1) {
            p1a += __shfl_xor_sync(0xffffffffu, p1a, o);
            p2a += __shfl_xor_sync(0xffffffffu, p2a, o);
            p1b += __shfl_xor_sync(0xffffffffu, p1b, o);
            p2b += __shfl_xor_sync(0xffffffffu, p2b, o);
        }
        if ((lane & 3) == 0) {
            ps1[nbh * 64 + r0] = p1a;  ps2[nbh * 64 + r0] = p2a;
            ps1[nbh * 64 + r1] = p1b;  ps2[nbh * 64 + r1] = p2b;
        }
    }
    __syncthreads();
    if (tid < 64) {
        d_s1[rowBase + tid] = ps1[tid] + ps1[64 + tid];
        d_s2[rowBase + tid] = ps2[tid] + ps2[64 + tid];
    }
}

// ------- K2a: hybrid register/shuffle bitonic sort (R8 version, no fusion) -----
__global__ void __launch_bounds__(1024) k_sort()
{
    __shared__ float sk[NTOK];
    __shared__ int   sx[NTOK];
    __shared__ float wsum[64];

    const int role = blockIdx.x, b = blockIdx.y, tid = threadIdx.x;
    const int lane = tid & 31, wid = tid >> 5;
    const float* src = (role == 0 ? d_s1 : d_s2) + b * NTOK;

    float2 v0 = *(const float2*)&src[2 * tid];
    float k0 = v0.x, k1 = v0.y;
    int   x0 = 2 * tid, x1 = 2 * tid + 1;

    #pragma unroll
    for (int k = 2; k <= 64; k <<= 1) {
        const bool up = (((tid << 1) & k) == 0);
        #pragma unroll
        for (int j = k >> 1; j >= 2; j >>= 1) {
            const int m = j >> 1;
            float pk0 = __shfl_xor_sync(~0u, k0, m);
            float pk1 = __shfl_xor_sync(~0u, k1, m);
            int   px0 = __shfl_xor_sync(~0u, x0, m);
            int   px1 = __shfl_xor_sync(~0u, x1, m);
            const bool lo = ((tid & m) == 0);
            float lk = lo ? k0 : pk0, hk = lo ? pk0 : k0;
            if ((lk > hk) == up) { k0 = pk0; x0 = px0; }
            lk = lo ? k1 : pk1; hk = lo ? pk1 : k1;
            if ((lk > hk) == up) { k1 = pk1; x1 = px1; }
        }
        if ((k0 > k1) == up) {
            float tk = k0; k0 = k1; k1 = tk;
            int   tx = x0; x0 = x1; x1 = tx;
        }
    }

    #pragma unroll 1
    for (int k = 128; k <= 2048; k <<= 1) {
        sk[2 * tid] = k0; sk[2 * tid + 1] = k1;
        sx[2 * tid] = x0; sx[2 * tid + 1] = x1;
        __syncthreads();
        #pragma unroll 1
        for (int j = k >> 1; j >= 64; j >>= 1) {
            if ((tid & (j >> 1)) == 0) {
                const bool up = (((tid << 1) & k) == 0);
                #pragma unroll
                for (int bb = 0; bb < 2; bb++) {
                    int i = 2 * tid + bb, p = i ^ j;
                    float A = sk[i], Bv = sk[p];
                    if ((A > Bv) == up) {
                        sk[i] = Bv; sk[p] = A;
                        int tI = sx[i]; sx[i] = sx[p]; sx[p] = tI;
                    }
                }
            }
            __syncthreads();
        }
        k0 = sk[2 * tid]; k1 = sk[2 * tid + 1];
        x0 = sx[2 * tid]; x1 = sx[2 * tid + 1];
        const bool up = (((tid << 1) & k) == 0);
        #pragma unroll
        for (int j = 32; j >= 2; j >>= 1) {
            const int m = j >> 1;
            float pk0 = __shfl_xor_sync(~0u, k0, m);
            float pk1 = __shfl_xor_sync(~0u, k1, m);
            int   px0 = __shfl_xor_sync(~0u, x0, m);
            int   px1 = __shfl_xor_sync(~0u, x1, m);
            const bool lo = ((tid & m) == 0);
            float lk = lo ? k0 : pk0, hk = lo ? pk0 : k0;
            if ((lk > hk) == up) { k0 = pk0; x0 = px0; }
            lk = lo ? k1 : pk1; hk = lo ? pk1 : k1;
            if ((lk > hk) == up) { k1 = pk1; x1 = px1; }
        }
        if ((k0 > k1) == up) {
            float tk = k0; k0 = k1; k1 = tk;
            int   tx = x0; x0 = x1; x1 = tx;
        }
    }

    if (role == 1) {
        *(float2*)&d_s2s[b * NTOK + 2 * tid]  = make_float2(k0, k1);
        *(int2*)  &d_perm[b * NTOK + 2 * tid] = make_int2(x0, x1);
        return;
    }

    const float e0 = expf(k0), e1 = expf(k1);
    const float a0 = expf(ALPHA * k0), a1 = expf(ALPHA * k1);
    float ie = e0 + e1, ia = a0 + a1;
    #pragma unroll
    for (int o = 1; o < 32; o <<= 1) {
        float te = __shfl_up_sync(~0u, ie, o);
        float ta = __shfl_up_sync(~0u, ia, o);
        if (lane >= o) { ie += te; ia += ta; }
    }
    if (lane == 31) { wsum[wid] = ie; wsum[32 + wid] = ia; }
    __syncthreads();
    if (wid == 0) {
        float we = wsum[lane], wa = wsum[32 + lane];
        #pragma unroll
        for (int o = 1; o < 32; o <<= 1) {
            float te = __shfl_up_sync(~0u, we, o);
            float ta = __shfl_up_sync(~0u, wa, o);
            if (lane >= o) { we += te; wa += ta; }
        }
        wsum[lane] = we; wsum[32 + lane] = wa;
    }
    __syncthreads();
    const float offE = (wid > 0 ? wsum[wid - 1] : 0.f);
    const float offA = (wid > 0 ? wsum[32 + wid - 1] : 0.f);
    const float peI = offE + ie;
    const float paI = offA + ia;

    *(float2*)&d_ss1[b * NTOK + 2 * tid] = make_float2(k0, k1);
    *(float2*)&d_pe[b * NTOK + 2 * tid]  = make_float2(peI - e1, peI);
    *(float2*)&d_pa[b * NTOK + 2 * tid]  = make_float2(paI - a1, paI);
}

// ------- K2b: smem-staged searches, wide grid (8, B, 2) x 256 ------------------
// z==0: stage ss1, compute j-side g1/g2. z==1: stage ss2, compute i-side tq/exps.
__global__ void __launch_bounds__(256) k_gfill()
{
    __shared__ float sarr[NTOK];

    const int b = blockIdx.y, tid = threadIdx.x;
    const int idx = blockIdx.x * 256 + tid;
    const float* stage_src = (blockIdx.z == 0 ? d_ss1 : d_s2s) + b * NTOK;

    #pragma unroll
    for (int l = 0; l < 2; l++) {
        int f4 = tid + l * 256;
        *(float4*)&sarr[f4 * 4] = *(const float4*)&stage_src[f4 * 4];
    }
    __syncthreads();

    if (blockIdx.z == 0) {
        float s2v = __ldg(&d_s2s[b * NTOK + idx]);
        float keyv = -s2v;
        int lo = 0;
        #pragma unroll
        for (int step = 1024; step >= 1; step >>= 1) {
            int probe = lo + step - 1;
            if (probe < NTOK && sarr[probe] < keyv) lo += step;
        }
        const float totE = __ldg(&d_pe[b * NTOK + NTOK - 1]);
        float preE = lo > 0 ? __ldg(&d_pe[b * NTOK + lo - 1]) : 0.f;
        float preA = lo > 0 ? __ldg(&d_pa[b * NTOK + lo - 1]) : 0.f;
        float e2  = expf(s2v);
        float ea2 = expf(ALPHA * s2v);
        float inv = 1.f / (e2 * (totE - preE) + ea2 * preA);
        d_g1[b * NTOK + idx] = e2  * inv;
        d_g2[b * NTOK + idx] = ea2 * inv;
    } else {
        float s1v = __ldg(&d_s1[b * NTOK + idx]);
        float keyv = -s1v;
        int lo = 0;
        #pragma unroll
        for (int step = 1024; step >= 1; step >>= 1) {
            int probe = lo + step - 1;
            if (probe < NTOK && sarr[probe] < keyv) lo += step;
        }
        d_tq[b * NTOK + idx] = lo;
        d_e1[b * NTOK + idx] = expf(s1v);
        d_e2[b * NTOK + idx] = expf(ALPHA * s1v);
    }
}

// ------- K3: chunk-local prefix sums, interleaved STG.64 stores ----------------
__global__ void __launch_bounds__(128) k_scan()
{
    __shared__ int   sp[CHUNK];
    __shared__ float sg1[CHUNK], sg2[CHUNK];

    const int b = blockIdx.y, c = blockIdx.x, d = threadIdx.x;
    const int base = b * NTOK + c * CHUNK;

    if (d < CHUNK)           sp [d]             = d_perm[base + d];
    else if (d < 2 * CHUNK)  sg1[d - CHUNK]     = d_g1[base + d - CHUNK];
    else if (d < 3 * CHUNK)  sg2[d - 2 * CHUNK] = d_g2[base + d - 2 * CHUNK];
    __syncthreads();

    float w[CHUNK];
    #pragma unroll
    for (int r = 0; r < CHUNK; r++)
        w[r] = d_Wh[((size_t)b * NTOK + sp[r]) * D + d];

    float s1a = 0.f, s2a = 0.f;
    #pragma unroll
    for (int r = 0; r < CHUNK; r++) {
        s1a += sg1[r] * w[r];
        s2a += sg2[r] * w[r];
        *(float2*)&d_loc12[((size_t)(base + r) * D + d) * 2] = make_float2(s1a, s2a);
    }
    d_ct1[(b * NCHUNK + c) * D + d] = s1a;
    d_ct2[(b * NCHUNK + c) * D + d] = s2a;
}

// ------- K4: two-phase exclusive scan of 128 chunk totals ---------------------
__global__ void __launch_bounds__(1024) k_coff()
{
    __shared__ float part1[8][D];
    __shared__ float part2[8][D];

    const int b = blockIdx.x;
    const int d = threadIdx.x & 127;
    const int g = threadIdx.x >> 7;

    float v1[16], v2[16];
    #pragma unroll
    for (int r = 0; r < 16; r++) {
        int c = g * 16 + r;
        v1[r] = d_ct1[(b * NCHUNK + c) * D + d];
        v2[r] = d_ct2[(b * NCHUNK + c) * D + d];
    }
    float run1 = 0.f, run2 = 0.f;
    #pragma unroll
    for (int r = 0; r < 16; r++) {
        float t1 = v1[r]; v1[r] = run1; run1 += t1;
        float t2 = v2[r]; v2[r] = run2; run2 += t2;
    }
    part1[g][d] = run1;
    part2[g][d] = run2;
    __syncthreads();

    if (g == 0) {
        float r1 = 0.f, r2 = 0.f;
        #pragma unroll
        for (int gg = 0; gg < 8; gg++) {
            float t1 = part1[gg][d]; part1[gg][d] = r1; r1 += t1;
            float t2 = part2[gg][d]; part2[gg][d] = r2; r2 += t2;
        }
        d_tot1[b * D + d] = r1;
    }
    __syncthreads();

    const float o1 = part1[g][d];
    const float o2 = part2[g][d];
    #pragma unroll
    for (int r = 0; r < 16; r++) {
        int c = g * 16 + r;
        *(float2*)&d_cp12[((size_t)(b * NCHUNK + c) * D + d) * 2] = make_float2(o1 + v1[r], o2 + v2[r]);
    }
}

// ------- K5: wide gather + ELU (interleaved loc/cp reads) ----------------------
__global__ void __launch_bounds__(256) k_out(float* __restrict__ out)
{
    const int gq   = blockIdx.x * 8 + (threadIdx.x >> 5);
    const int lane = threadIdx.x & 31;
    const int b    = gq >> 11;
    const int d4   = lane * 4;

    const int   t  = d_tq[gq];
    const float e1 = d_e1[gq];
    const float e2 = d_e2[gq];

    float4 tot = *(const float4*)&d_tot1[b * D + d4];
    float4 P1 = {0.f, 0.f, 0.f, 0.f};
    float4 P2 = {0.f, 0.f, 0.f, 0.f};

    if (t > 0) {
        int k = t - 1;
        int c = k >> 4;
        size_t kb = ((size_t)(b * NTOK + k) * D + d4) * 2;
        size_t cb = ((size_t)(b * NCHUNK + c) * D + d4) * 2;
        float4 u0 = *(const float4*)&d_loc12[kb];
        float4 u1 = *(const float4*)&d_loc12[kb + 4];
        float4 q0 = *(const float4*)&d_cp12[cb];
        float4 q1 = *(const float4*)&d_cp12[cb + 4];
        P1.x = u0.x + q0.x; P2.x = u0.y + q0.y;
        P1.y = u0.z + q0.z; P2.y = u0.w + q0.w;
        P1.z = u1.x + q1.x; P2.z = u1.y + q1.y;
        P1.w = u1.z + q1.z; P2.w = u1.w + q1.w;
    }

    float4 v;
    v.x = e1 * (tot.x - P1.x) + e2 * P2.x;
    v.y = e1 * (tot.y - P1.y) + e2 * P2.y;
    v.z = e1 * (tot.z - P1.z) + e2 * P2.z;
    v.w = e1 * (tot.w - P1.w) + e2 * P2.w;
    v.x = v.x > 0.f ? v.x : expm1f(v.x);
    v.y = v.y > 0.f ? v.y : expm1f(v.y);
    v.z = v.z > 0.f ? v.z : expm1f(v.z);
    v.w = v.w > 0.f ? v.w : expm1f(v.w);

    *(float4*)&out[(size_t)gq * D + d4] = v;
}

// -----------------------------------------------------------------------------
extern "C" void kernel_launch(void* const* d_in, const int* in_sizes, int n_in,
                              void* d_out, int out_size)
{
    const float* h = (const float*)d_in[0];   // [8,2048,256]
    const float* W = (const float*)d_in[1];   // [256,128]
    const float* a = (const float*)d_in[2];   // [256,1]
    float* out = (float*)d_out;               // [8,2048,128]

    cudaFuncSetAttribute(k_gemm_mma, cudaFuncAttributeMaxDynamicSharedMemorySize, SM_TOT);

    k_wconv<<<FIN * D / 256, 256>>>(W);
    k_gemm_mma<<<(B * NTOK) / 64, 256, SM_TOT>>>(h, a);
    k_sort <<<dim3(2, B), 1024>>>();
    k_gfill<<<dim3(8, B, 2), 256>>>();
    k_scan <<<dim3(NCHUNK, B), 128>>>();
    k_coff <<<B, 1024>>>();
    k_out  <<<(B * NTOK) / 8, 256>>>(out);
}

// round 11
// speedup vs baseline: 1.0868x; 1.0007x over previous
#include <cuda_runtime.h>
#include <cuda_bf16.h>
#include <math.h>
#include <stdint.h>

#define B    8
#define NTOK 2048
#define FIN  256
#define D    128
#define ALPHA 0.2f
#define CHUNK  16
#define NCHUNK (NTOK/CHUNK)   // 128

// ---------------- scratch (__device__ globals) --------------------------------
__device__ float d_Wh[B*NTOK*D];
__device__ float d_s1[B*NTOK];
__device__ float d_s2[B*NTOK];
__device__ float d_ss1[B*NTOK];
__device__ float d_pe[B*NTOK];
__device__ float d_pa[B*NTOK];
__device__ float d_s2s[B*NTOK];
__device__ int   d_perm[B*NTOK];
__device__ float d_g1[B*NTOK];
__device__ float d_g2[B*NTOK];
__device__ int   d_tq[B*NTOK];
__device__ float d_e1[B*NTOK];
__device__ float d_e2[B*NTOK];
__device__ float d_loc12[B*NTOK*D*2];      // interleaved (v1,v2) prefix pairs
__device__ float d_ct1[B*NCHUNK*D];
__device__ float d_ct2[B*NCHUNK*D];
__device__ float d_cp12[B*NCHUNK*D*2];     // interleaved chunk offsets
__device__ float d_tot1[B*D];
__device__ __nv_bfloat16 d_Wt_hi[D*FIN];
__device__ __nv_bfloat16 d_Wt_lo[D*FIN];

// ================= mma.sync helpers ============================================
__device__ __forceinline__ uint32_t smem_u32(const void* p) {
    uint32_t a;
    asm("{ .reg .u64 t; cvta.to.shared.u64 t, %1; cvt.u32.u64 %0, t; }" : "=r"(a) : "l"(p));
    return a;
}
__device__ __forceinline__ void ldm_x4(uint32_t& r0, uint32_t& r1, uint32_t& r2, uint32_t& r3, uint32_t addr) {
    asm volatile("ldmatrix.sync.aligned.m8n8.x4.shared.b16 {%0,%1,%2,%3}, [%4];"
        : "=r"(r0), "=r"(r1), "=r"(r2), "=r"(r3) : "r"(addr));
}
__device__ __forceinline__ void mma_bf16(float* c, const uint32_t* a, uint32_t b0, uint32_t b1) {
    asm volatile("mma.sync.aligned.m16n8k16.row.col.f32.bf16.bf16.f32 "
        "{%0,%1,%2,%3},{%4,%5,%6,%7},{%8,%9},{%0,%1,%2,%3};"
        : "+f"(c[0]), "+f"(c[1]), "+f"(c[2]), "+f"(c[3])
        : "r"(a[0]), "r"(a[1]), "r"(a[2]), "r"(a[3]), "r"(b0), "r"(b1));
}

// smem layout (bytes). Rows padded to 72 bf16 (144 B).
#define KT      64
#define ROWB    144
#define AH_OFF  0
#define AL_OFF  9216
#define BH_OFF  18432
#define BL_OFF  36864
#define A1_OFF  55296
#define A2_OFF  55808
#define PS1_OFF 56320
#define PS2_OFF 56832
#define SM_TOT  57344

// ---------------- K0: W -> bf16 hi/lo, transposed [n][k] ----------------------
__global__ void __launch_bounds__(256) k_wconv(const float* __restrict__ W)
{
    int idx = blockIdx.x * 256 + threadIdx.x;
    int k = idx & 255;
    int n = idx >> 8;
    float x = W[(size_t)k * D + n];
    __nv_bfloat16 hi = __float2bfloat16_rn(x);
    __nv_bfloat16 lo = __float2bfloat16_rn(x - __bfloat162float(hi));
    d_Wt_hi[n * FIN + k] = hi;
    d_Wt_lo[n * FIN + k] = lo;
}

// ---------------- K1: Wh = h@W via mma.sync bf16x3 (64x128 tile) --------------
__global__ void __launch_bounds__(256, 2)
k_gemm_mma(const float* __restrict__ h, const float* __restrict__ a)
{
    extern __shared__ char smem[];
    const uint32_t sb = smem_u32(smem);
    const int tid  = threadIdx.x;
    const int wid  = tid >> 5;
    const int lane = tid & 31;
    const int rowBase = blockIdx.x * 64;

    float* a1s = (float*)(smem + A1_OFF);
    float* a2s = (float*)(smem + A2_OFF);
    float* ps1 = (float*)(smem + PS1_OFF);
    float* ps2 = (float*)(smem + PS2_OFF);

    if (tid < 128) {
        a1s[tid] = a[tid];
        a2s[tid] = a[128 + tid];
    }

    const int mb0 = (wid & 3) * 16;
    const int nbh = wid >> 2;
    const int nb  = nbh * 64;

    float acc[8][4] = {};

    for (int t = 0; t < 4; t++) {
        const int kt = t * KT;
        __syncthreads();

        #pragma unroll
        for (int l = 0; l < 4; l++) {
            int f4 = tid + l * 256;
            int r  = f4 >> 4;
            int c  = (f4 & 15) * 4;
            float4 v = *(const float4*)&h[(size_t)(rowBase + r) * FIN + kt + c];
            __nv_bfloat162 h0 = __floats2bfloat162_rn(v.x, v.y);
            __nv_bfloat162 h1 = __floats2bfloat162_rn(v.z, v.w);
            __nv_bfloat162 l0 = __floats2bfloat162_rn(v.x - __bfloat162float(h0.x),
                                                      v.y - __bfloat162float(h0.y));
            __nv_bfloat162 l1 = __floats2bfloat162_rn(v.z - __bfloat162float(h1.x),
                                                      v.w - __bfloat162float(h1.y));
            uint32_t off = (uint32_t)r * ROWB + (uint32_t)c * 2;
            *(uint2*)(smem + AH_OFF + off) = make_uint2(*(uint32_t*)&h0, *(uint32_t*)&h1);
            *(uint2*)(smem + AL_OFF + off) = make_uint2(*(uint32_t*)&l0, *(uint32_t*)&l1);
        }
        #pragma unroll
        for (int l = 0; l < 4; l++) {
            int u  = tid + l * 256;
            int n  = u >> 3;
            int ch = (u & 7) * 16;
            uint32_t dst = (uint32_t)n * ROWB + (uint32_t)ch;
            const char* srch = (const char*)&d_Wt_hi[n * FIN + kt] + ch;
            const char* srcl = (const char*)&d_Wt_lo[n * FIN + kt] + ch;
            *(uint4*)(smem + BH_OFF + dst) = *(const uint4*)srch;
            *(uint4*)(smem + BL_OFF + dst) = *(const uint4*)srcl;
        }
        __syncthreads();

        #pragma unroll
        for (int ks = 0; ks < 4; ks++) {
            const uint32_t colB = (uint32_t)ks * 32 + (uint32_t)(lane >> 4) * 16;
            uint32_t a_hi[4], a_lo[4];
            {
                uint32_t roff = (uint32_t)(mb0 + (lane & 15)) * ROWB + colB;
                ldm_x4(a_hi[0], a_hi[1], a_hi[2], a_hi[3], sb + AH_OFF + roff);
                ldm_x4(a_lo[0], a_lo[1], a_lo[2], a_lo[3], sb + AL_OFF + roff);
            }
            #pragma unroll
            for (int g = 0; g < 4; g++) {
                uint32_t roff = (uint32_t)(nb + g * 16 + (lane & 15)) * ROWB + colB;
                uint32_t b0, b1, b2, b3;
                ldm_x4(b0, b1, b2, b3, sb + BH_OFF + roff);
                mma_bf16(acc[g * 2],     a_hi, b0, b2);
                mma_bf16(acc[g * 2 + 1], a_hi, b1, b3);
                mma_bf16(acc[g * 2],     a_lo, b0, b2);
                mma_bf16(acc[g * 2 + 1], a_lo, b1, b3);
                ldm_x4(b0, b1, b2, b3, sb + BL_OFF + roff);
                mma_bf16(acc[g * 2],     a_hi, b0, b2);
                mma_bf16(acc[g * 2 + 1], a_hi, b1, b3);
            }
        }
    }
    __syncthreads();

    {
        const int r0 = mb0 + (lane >> 2);
        const int r1 = r0 + 8;
        float p1a = 0.f, p2a = 0.f, p1b = 0.f, p2b = 0.f;
        #pragma unroll
        for (int nt = 0; nt < 8; nt++) {
            const int col = nb + nt * 8 + (lane & 3) * 2;
            float c0 = acc[nt][0], c1 = acc[nt][1];
            float c2 = acc[nt][2], c3 = acc[nt][3];
            *(float2*)&d_Wh[(size_t)(rowBase + r0) * D + col] = make_float2(c0, c1);
            *(float2*)&d_Wh[(size_t)(rowBase + r1) * D + col] = make_float2(c2, c3);
            p1a += c0 * a1s[col] + c1 * a1s[col + 1];
            p2a += c0 * a2s[col] + c1 * a2s[col + 1];
            p1b += c2 * a1s[col] + c3 * a1s[col + 1];
            p2b += c2 * a2s[col] + c3 * a2s[col + 1];
        }
        #pragma unroll
        for (int o = 1; o <= 2; o <<= 1) {
            p1a += __shfl_xor_sync(0xffffffffu, p1a, o);
            p2a += __shfl_xor_sync(0xffffffffu, p2a, o);
            p1b += __shfl_xor_sync(0xffffffffu, p1b, o);
            p2b += __shfl_xor_sync(0xffffffffu, p2b, o);
        }
        if ((lane & 3) == 0) {
            ps1[nbh * 64 + r0] = p1a;  ps2[nbh * 64 + r0] = p2a;
            ps1[nbh * 64 + r1] = p1b;  ps2[nbh * 64 + r1] = p2b;
        }
    }
    __syncthreads();
    if (tid < 64) {
        d_s1[rowBase + tid] = ps1[tid] + ps1[64 + tid];
        d_s2[rowBase + tid] = ps2[tid] + ps2[64 + tid];
    }
}

// ------- K2a: hybrid register/shuffle bitonic sort -----------------------------
__global__ void __launch_bounds__(1024) k_sort()
{
    __shared__ float sk[NTOK];
    __shared__ int   sx[NTOK];
    __shared__ float wsum[64];

    const int role = blockIdx.x, b = blockIdx.y, tid = threadIdx.x;
    const int lane = tid & 31, wid = tid >> 5;
    const float* src = (role == 0 ? d_s1 : d_s2) + b * NTOK;

    float2 v0 = *(const float2*)&src[2 * tid];
    float k0 = v0.x, k1 = v0.y;
    int   x0 = 2 * tid, x1 = 2 * tid + 1;

    #pragma unroll
    for (int k = 2; k <= 64; k <<= 1) {
        const bool up = (((tid << 1) & k) == 0);
        #pragma unroll
        for (int j = k >> 1; j >= 2; j >>= 1) {
            const int m = j >> 1;
            float pk0 = __shfl_xor_sync(~0u, k0, m);
            float pk1 = __shfl_xor_sync(~0u, k1, m);
            int   px0 = __shfl_xor_sync(~0u, x0, m);
            int   px1 = __shfl_xor_sync(~0u, x1, m);
            const bool lo = ((tid & m) == 0);
            float lk = lo ? k0 : pk0, hk = lo ? pk0 : k0;
            if ((lk > hk) == up) { k0 = pk0; x0 = px0; }
            lk = lo ? k1 : pk1; hk = lo ? pk1 : k1;
            if ((lk > hk) == up) { k1 = pk1; x1 = px1; }
        }
        if ((k0 > k1) == up) {
            float tk = k0; k0 = k1; k1 = tk;
            int   tx = x0; x0 = x1; x1 = tx;
        }
    }

    #pragma unroll 1
    for (int k = 128; k <= 2048; k <<= 1) {
        sk[2 * tid] = k0; sk[2 * tid + 1] = k1;
        sx[2 * tid] = x0; sx[2 * tid + 1] = x1;
        __syncthreads();
        #pragma unroll 1
        for (int j = k >> 1; j >= 64; j >>= 1) {
            if ((tid & (j >> 1)) == 0) {
                const bool up = (((tid << 1) & k) == 0);
                #pragma unroll
                for (int bb = 0; bb < 2; bb++) {
                    int i = 2 * tid + bb, p = i ^ j;
                    float A = sk[i], Bv = sk[p];
                    if ((A > Bv) == up) {
                        sk[i] = Bv; sk[p] = A;
                        int tI = sx[i]; sx[i] = sx[p]; sx[p] = tI;
                    }
                }
            }
            __syncthreads();
        }
        k0 = sk[2 * tid]; k1 = sk[2 * tid + 1];
        x0 = sx[2 * tid]; x1 = sx[2 * tid + 1];
        const bool up = (((tid << 1) & k) == 0);
        #pragma unroll
        for (int j = 32; j >= 2; j >>= 1) {
            const int m = j >> 1;
            float pk0 = __shfl_xor_sync(~0u, k0, m);
            float pk1 = __shfl_xor_sync(~0u, k1, m);
            int   px0 = __shfl_xor_sync(~0u, x0, m);
            int   px1 = __shfl_xor_sync(~0u, x1, m);
            const bool lo = ((tid & m) == 0);
            float lk = lo ? k0 : pk0, hk = lo ? pk0 : k0;
            if ((lk > hk) == up) { k0 = pk0; x0 = px0; }
            lk = lo ? k1 : pk1; hk = lo ? pk1 : k1;
            if ((lk > hk) == up) { k1 = pk1; x1 = px1; }
        }
        if ((k0 > k1) == up) {
            float tk = k0; k0 = k1; k1 = tk;
            int   tx = x0; x0 = x1; x1 = tx;
        }
    }

    if (role == 1) {
        *(float2*)&d_s2s[b * NTOK + 2 * tid]  = make_float2(k0, k1);
        *(int2*)  &d_perm[b * NTOK + 2 * tid] = make_int2(x0, x1);
        return;
    }

    const float e0 = expf(k0), e1 = expf(k1);
    const float a0 = expf(ALPHA * k0), a1 = expf(ALPHA * k1);
    float ie = e0 + e1, ia = a0 + a1;
    #pragma unroll
    for (int o = 1; o < 32; o <<= 1) {
        float te = __shfl_up_sync(~0u, ie, o);
        float ta = __shfl_up_sync(~0u, ia, o);
        if (lane >= o) { ie += te; ia += ta; }
    }
    if (lane == 31) { wsum[wid] = ie; wsum[32 + wid] = ia; }
    __syncthreads();
    if (wid == 0) {
        float we = wsum[lane], wa = wsum[32 + lane];
        #pragma unroll
        for (int o = 1; o < 32; o <<= 1) {
            float te = __shfl_up_sync(~0u, we, o);
            float ta = __shfl_up_sync(~0u, wa, o);
            if (lane >= o) { we += te; wa += ta; }
        }
        wsum[lane] = we; wsum[32 + lane] = wa;
    }
    __syncthreads();
    const float offE = (wid > 0 ? wsum[wid - 1] : 0.f);
    const float offA = (wid > 0 ? wsum[32 + wid - 1] : 0.f);
    const float peI = offE + ie;
    const float paI = offA + ia;

    *(float2*)&d_ss1[b * NTOK + 2 * tid] = make_float2(k0, k1);
    *(float2*)&d_pe[b * NTOK + 2 * tid]  = make_float2(peI - e1, peI);
    *(float2*)&d_pa[b * NTOK + 2 * tid]  = make_float2(paI - a1, paI);
}

// ------- K2b: fully smem-staged searches + prefix lookups ----------------------
// z==0: stage ss1 + pe + pa, compute j-side g1/g2. z==1: stage ss2, i-side.
__global__ void __launch_bounds__(256) k_gfill()
{
    __shared__ float sarr[NTOK];
    __shared__ float spe[NTOK];
    __shared__ float spa[NTOK];

    const int b = blockIdx.y, tid = threadIdx.x;
    const int idx = blockIdx.x * 256 + tid;

    if (blockIdx.z == 0) {
        #pragma unroll
        for (int l = 0; l < 2; l++) {
            int f4 = tid + l * 256;
            *(float4*)&sarr[f4 * 4] = *(const float4*)&d_ss1[b * NTOK + f4 * 4];
            *(float4*)&spe[f4 * 4]  = *(const float4*)&d_pe[b * NTOK + f4 * 4];
            *(float4*)&spa[f4 * 4]  = *(const float4*)&d_pa[b * NTOK + f4 * 4];
        }
        __syncthreads();

        float s2v = __ldg(&d_s2s[b * NTOK + idx]);
        float keyv = -s2v;
        int lo = 0;
        #pragma unroll
        for (int step = 1024; step >= 1; step >>= 1) {
            int probe = lo + step - 1;
            if (probe < NTOK && sarr[probe] < keyv) lo += step;
        }
        const float totE = spe[NTOK - 1];
        float preE = lo > 0 ? spe[lo - 1] : 0.f;
        float preA = lo > 0 ? spa[lo - 1] : 0.f;
        float e2  = expf(s2v);
        float ea2 = expf(ALPHA * s2v);
        float inv = 1.f / (e2 * (totE - preE) + ea2 * preA);
        d_g1[b * NTOK + idx] = e2  * inv;
        d_g2[b * NTOK + idx] = ea2 * inv;
    } else {
        #pragma unroll
        for (int l = 0; l < 2; l++) {
            int f4 = tid + l * 256;
            *(float4*)&sarr[f4 * 4] = *(const float4*)&d_s2s[b * NTOK + f4 * 4];
        }
        __syncthreads();

        float s1v = __ldg(&d_s1[b * NTOK + idx]);
        float keyv = -s1v;
        int lo = 0;
        #pragma unroll
        for (int step = 1024; step >= 1; step >>= 1) {
            int probe = lo + step - 1;
            if (probe < NTOK && sarr[probe] < keyv) lo += step;
        }
        d_tq[b * NTOK + idx] = lo;
        d_e1[b * NTOK + idx] = expf(s1v);
        d_e2[b * NTOK + idx] = expf(ALPHA * s1v);
    }
}

// ------- K3: prefix sums, 2 dims/thread, STG.128 stores, 2 chunks/block --------
__global__ void __launch_bounds__(128) k_scan()
{
    __shared__ int   sp[2][CHUNK];
    __shared__ float sg1[2][CHUNK], sg2[2][CHUNK];

    const int b    = blockIdx.y;
    const int half = threadIdx.x >> 6;          // chunk within block
    const int t64  = threadIdx.x & 63;
    const int c    = blockIdx.x * 2 + half;
    const int base = b * NTOK + c * CHUNK;
    const int d0   = t64 * 2;

    if (t64 < CHUNK) {
        sp [half][t64] = d_perm[base + t64];
        sg1[half][t64] = d_g1[base + t64];
        sg2[half][t64] = d_g2[base + t64];
    }
    __syncthreads();

    float2 w[CHUNK];
    #pragma unroll
    for (int r = 0; r < CHUNK; r++)
        w[r] = *(const float2*)&d_Wh[((size_t)b * NTOK + sp[half][r]) * D + d0];

    float s1a = 0.f, s2a = 0.f, s1b = 0.f, s2b = 0.f;
    #pragma unroll
    for (int r = 0; r < CHUNK; r++) {
        float g1 = sg1[half][r], g2 = sg2[half][r];
        s1a += g1 * w[r].x;  s2a += g2 * w[r].x;
        s1b += g1 * w[r].y;  s2b += g2 * w[r].y;
        *(float4*)&d_loc12[((size_t)(base + r) * D + d0) * 2] = make_float4(s1a, s2a, s1b, s2b);
    }
    const int cb = (b * NCHUNK + c) * D + d0;
    *(float2*)&d_ct1[cb] = make_float2(s1a, s1b);
    *(float2*)&d_ct2[cb] = make_float2(s2a, s2b);
}

// ------- K4: two-phase exclusive scan of 128 chunk totals ---------------------
__global__ void __launch_bounds__(1024) k_coff()
{
    __shared__ float part1[8][D];
    __shared__ float part2[8][D];

    const int b = blockIdx.x;
    const int d = threadIdx.x & 127;
    const int g = threadIdx.x >> 7;

    float v1[16], v2[16];
    #pragma unroll
    for (int r = 0; r < 16; r++) {
        int c = g * 16 + r;
        v1[r] = d_ct1[(b * NCHUNK + c) * D + d];
        v2[r] = d_ct2[(b * NCHUNK + c) * D + d];
    }
    float run1 = 0.f, run2 = 0.f;
    #pragma unroll
    for (int r = 0; r < 16; r++) {
        float t1 = v1[r]; v1[r] = run1; run1 += t1;
        float t2 = v2[r]; v2[r] = run2; run2 += t2;
    }
    part1[g][d] = run1;
    part2[g][d] = run2;
    __syncthreads();

    if (g == 0) {
        float r1 = 0.f, r2 = 0.f;
        #pragma unroll
        for (int gg = 0; gg < 8; gg++) {
            float t1 = part1[gg][d]; part1[gg][d] = r1; r1 += t1;
            float t2 = part2[gg][d]; part2[gg][d] = r2; r2 += t2;
        }
        d_tot1[b * D + d] = r1;
    }
    __syncthreads();

    const float o1 = part1[g][d];
    const float o2 = part2[g][d];
    #pragma unroll
    for (int r = 0; r < 16; r++) {
        int c = g * 16 + r;
        *(float2*)&d_cp12[((size_t)(b * NCHUNK + c) * D + d) * 2] = make_float2(o1 + v1[r], o2 + v2[r]);
    }
}

// ------- K5: wide gather + ELU (interleaved loc/cp reads) ----------------------
__global__ void __launch_bounds__(256) k_out(float* __restrict__ out)
{
    const int gq   = blockIdx.x * 8 + (threadIdx.x >> 5);
    const int lane = threadIdx.x & 31;
    const int b    = gq >> 11;
    const int d4   = lane * 4;

    const int   t  = d_tq[gq];
    const float e1 = d_e1[gq];
    const float e2 = d_e2[gq];

    float4 tot = *(const float4*)&d_tot1[b * D + d4];
    float4 P1 = {0.f, 0.f, 0.f, 0.f};
    float4 P2 = {0.f, 0.f, 0.f, 0.f};

    if (t > 0) {
        int k = t - 1;
        int c = k >> 4;
        size_t kb = ((size_t)(b * NTOK + k) * D + d4) * 2;
        size_t cb = ((size_t)(b * NCHUNK + c) * D + d4) * 2;
        float4 u0 = *(const float4*)&d_loc12[kb];
        float4 u1 = *(const float4*)&d_loc12[kb + 4];
        float4 q0 = *(const float4*)&d_cp12[cb];
        float4 q1 = *(const float4*)&d_cp12[cb + 4];
        P1.x = u0.x + q0.x; P2.x = u0.y + q0.y;
        P1.y = u0.z + q0.z; P2.y = u0.w + q0.w;
        P1.z = u1.x + q1.x; P2.z = u1.y + q1.y;
        P1.w = u1.z + q1.z; P2.w = u1.w + q1.w;
    }

    float4 v;
    v.x = e1 * (tot.x - P1.x) + e2 * P2.x;
    v.y = e1 * (tot.y - P1.y) + e2 * P2.y;
    v.z = e1 * (tot.z - P1.z) + e2 * P2.z;
    v.w = e1 * (tot.w - P1.w) + e2 * P2.w;
    v.x = v.x > 0.f ? v.x : expm1f(v.x);
    v.y = v.y > 0.f ? v.y : expm1f(v.y);
    v.z = v.z > 0.f ? v.z : expm1f(v.z);
    v.w = v.w > 0.f ? v.w : expm1f(v.w);

    *(float4*)&out[(size_t)gq * D + d4] = v;
}

// -----------------------------------------------------------------------------
extern "C" void kernel_launch(void* const* d_in, const int* in_sizes, int n_in,
                              void* d_out, int out_size)
{
    const float* h = (const float*)d_in[0];   // [8,2048,256]
    const float* W = (const float*)d_in[1];   // [256,128]
    const float* a = (const float*)d_in[2];   // [256,1]
    float* out = (float*)d_out;               // [8,2048,128]

    cudaFuncSetAttribute(k_gemm_mma, cudaFuncAttributeMaxDynamicSharedMemorySize, SM_TOT);

    k_wconv<<<FIN * D / 256, 256>>>(W);
    k_gemm_mma<<<(B * NTOK) / 64, 256, SM_TOT>>>(h, a);
    k_sort <<<dim3(2, B), 1024>>>();
    k_gfill<<<dim3(8, B, 2), 256>>>();
    k_scan <<<dim3(NCHUNK / 2, B), 128>>>();
    k_coff <<<B, 1024>>>();
    k_out  <<<(B * NTOK) / 8, 256>>>(out);
}